// round 11
// baseline (speedup 1.0000x reference)
#include <cuda_runtime.h>

// ---- problem constants ----
#define SB      1024
#define N1      8192
#define N2      16384
#define NTERMS  (N1 + N2)          // 24576
#define NC      17                 // chunks
#define CHUNK   1448               // 16*1448 + 1408 = 24576
#define NSS     256
#define NT      512
#define ROWS    16
#define NCTR    (NC * SB)          // 17408 sublists, chunk-major: id = c*SB + s
#define NROLES  (2 * N1 + 3 * N2)  // 65536 list entries (exact, no padding)

// ---- persistent scratch (rebuilt every launch; structure is input-constant) ----
__device__ int g_cnt[NCTR];
__device__ int g_cur[NCTR];
__device__ int g_off[NCTR + 1];
__device__ unsigned g_list[NROLES];   // (species<<16) | (sign<<15) | localTermIdx

// dynamic smem: terms float4[CHUNK*4] | yq float4[4*SB] | dy float[16*SB]
#define SMEM_BYTES (CHUNK * 64 + 4 * SB * 16 + 16 * SB * 4)   // 223744

__inline__ __device__ float warp_red(float v) {
    #pragma unroll
    for (int o = 16; o > 0; o >>= 1) v += __shfl_xor_sync(0xFFFFFFFFu, v, o);
    return v;
}

// ---------- build kernels (3 launches) ----------
__device__ __forceinline__ void decode_role(
    int id, const int* p1, const int* r11, const int* p2,
    const int* r12, const int* r22, int& term, int& s, int& loss)
{
    if (id < N1)                 { term = id;                  s = __ldg(p1  + id);          loss = 0; }
    else if (id < 2 * N1)        { term = id - N1;             s = __ldg(r11 + id - N1);     loss = 1; }
    else if (id < 2 * N1 + N2)   { int j = id - 2 * N1;        term = N1 + j; s = __ldg(p2  + j); loss = 0; }
    else if (id < 2 * N1 + 2*N2) { int j = id - 2 * N1 - N2;   term = N1 + j; s = __ldg(r12 + j); loss = 1; }
    else                         { int j = id - 2 * N1 - 2*N2; term = N1 + j; s = __ldg(r22 + j); loss = 1; }
}

// g_cnt zero on entry (static zero-init at load; k_scan re-zeros each launch)
__global__ void k_count(const int* __restrict__ p1, const int* __restrict__ r11,
                        const int* __restrict__ p2, const int* __restrict__ r12,
                        const int* __restrict__ r22) {
    int id = blockIdx.x * blockDim.x + threadIdx.x;
    if (id >= NROLES) return;
    int term, s, loss;
    decode_role(id, p1, r11, p2, r12, r22, term, s, loss);
    int c = term / CHUNK;
    atomicAdd(&g_cnt[c * SB + s], 1);
}

__global__ void k_scan() {   // 1 CTA, 1024 threads; each scans 17 consecutive counters
    __shared__ int sh[1024];
    int t = threadIdx.x;
    int cnt[NC]; int tsum = 0;
    #pragma unroll
    for (int u = 0; u < NC; u++) {
        cnt[u] = g_cnt[t * NC + u];
        tsum += cnt[u];
    }
    sh[t] = tsum;
    __syncthreads();
    for (int o = 1; o < 1024; o <<= 1) {
        int x = (t >= o) ? sh[t - o] : 0;
        __syncthreads();
        sh[t] += x;
        __syncthreads();
    }
    int excl = sh[t] - tsum;
    #pragma unroll
    for (int u = 0; u < NC; u++) {
        g_off[t * NC + u] = excl;
        g_cur[t * NC + u] = excl;
        excl += cnt[u];
        g_cnt[t * NC + u] = 0;           // re-zero for next launch
    }
    if (t == 1023) g_off[NCTR] = sh[1023];
}

__global__ void k_fill(const int* __restrict__ p1, const int* __restrict__ r11,
                       const int* __restrict__ p2, const int* __restrict__ r12,
                       const int* __restrict__ r22) {
    int id = blockIdx.x * blockDim.x + threadIdx.x;
    if (id >= NROLES) return;
    int term, s, loss;
    decode_role(id, p1, r11, p2, r12, r22, term, s, loss);
    int c = term / CHUNK;
    int pos = atomicAdd(&g_cur[c * SB + s], 1);
    g_list[pos] = ((unsigned)s << 16) | ((unsigned)loss << 15) | (unsigned)(term - c * CHUNK);
}

// ---------- main kernel: 16 rows/CTA, grid=128, 1 CTA/SM, warp-stream gather ----------
__global__ __launch_bounds__(NT, 1) void three_phase_rhs(
    const float* __restrict__ t_in, const float* __restrict__ y_in,
    const float* __restrict__ den_gas,
    const float* __restrict__ a1, const float* __restrict__ g1,
    const float* __restrict__ a2, const float* __restrict__ g2,
    const int* __restrict__ r11, const int* __restrict__ r12,
    const int* __restrict__ r22,
    const int* __restrict__ inds_s, const int* __restrict__ inds_m,
    float* __restrict__ out)
{
    extern __shared__ float smemf[];
    float4* terms = (float4*)smemf;          // [CHUNK*4]: term jj -> 4 float4 (16 rows)
    float4* yq    = terms + CHUNK * 4;       // [4*SB]: yq[q*SB+s] = rows 4q..4q+3
    float*  dy    = (float*)(yq + 4 * SB);   // [16*SB]: dy[r*SB+s]
    __shared__ float red[48][NT / 32];
    __shared__ float tot[48];
    __shared__ float lossTot[16];

    const int tid  = threadIdx.x;
    const int lane = tid & 31;
    const int wid  = tid >> 5;               // 16 warps; warp owns species [wid*64, wid*64+64)
    const int b0   = blockIdx.x * ROWS;

    // load y (16 rows interleaved) + zero dy
    {
        const float* yr = y_in + (size_t)b0 * SB;
        for (int i = tid; i < SB; i += NT) {
            #pragma unroll
            for (int q = 0; q < 4; q++)
                yq[q * SB + i] = make_float4(yr[(4 * q + 0) * SB + i], yr[(4 * q + 1) * SB + i],
                                             yr[(4 * q + 2) * SB + i], yr[(4 * q + 3) * SB + i]);
        }
        float4* dy4 = (float4*)dy;
        for (int i = tid; i < 4 * SB; i += NT) dy4[i] = make_float4(0.f, 0.f, 0.f, 0.f);
        if (tid < 16) lossTot[tid] = 0.f;
    }

    float nI[ROWS], c2[ROWS];
    #pragma unroll
    for (int r = 0; r < ROWS; r++) {
        float T = 10.0f + 5.0f / (1.0f + __expf(-__ldg(t_in + b0 + r)));
        nI[r] = -1.0f / T;
        c2[r] = sqrtf(T * (1.0f / 300.0f)) * __ldg(den_gas + b0 + r);
    }
    const int s0 = __ldg(&inds_s[0]), m0 = __ldg(&inds_m[0]);
    __syncthreads();

    for (int c = 0; c < NC; c++) {
        const int base = c * CHUNK;
        const int clen = min(CHUNK, NTERMS - base);

        // ---- phase 1: terms for this chunk, 16 rows ----
        for (int jj = tid; jj < clen; jj += NT) {
            int j = base + jj;
            if (j < N1) {
                float a = __ldg(a1 + j), g = __ldg(g1 + j);
                int   rr = __ldg(r11 + j);
                #pragma unroll
                for (int q = 0; q < 4; q++) {
                    float4 yv = yq[q * SB + rr];
                    terms[jj * 4 + q] = make_float4(
                        a * __expf(g * nI[4 * q + 0]) * yv.x,
                        a * __expf(g * nI[4 * q + 1]) * yv.y,
                        a * __expf(g * nI[4 * q + 2]) * yv.z,
                        a * __expf(g * nI[4 * q + 3]) * yv.w);
                }
            } else {
                int j2 = j - N1;
                float a = __ldg(a2 + j2), g = __ldg(g2 + j2);
                int  rA = __ldg(r12 + j2), rB = __ldg(r22 + j2);
                #pragma unroll
                for (int q = 0; q < 4; q++) {
                    float4 ya = yq[q * SB + rA], yb = yq[q * SB + rB];
                    terms[jj * 4 + q] = make_float4(
                        a * c2[4 * q + 0] * __expf(g * nI[4 * q + 0]) * ya.x * yb.x,
                        a * c2[4 * q + 1] * __expf(g * nI[4 * q + 1]) * ya.y * yb.y,
                        a * c2[4 * q + 2] * __expf(g * nI[4 * q + 2]) * ya.z * yb.z,
                        a * c2[4 * q + 3] * __expf(g * nI[4 * q + 3]) * ya.w * yb.w);
                }
            }
        }
        __syncthreads();

        // ---- phase 2: warp-stream gather, lane-balanced (+/-1 entry) ----
        {
            const int segBeg = __ldg(&g_off[c * SB + wid * 64]);
            const int segEnd = __ldg(&g_off[c * SB + wid * 64 + 64]);
            const int len = segEnd - segBeg;
            const int lb = segBeg + (len * lane) / 32;
            const int le = segBeg + (len * (lane + 1)) / 32;

            int curS = -1; bool curSurf = false;
            float aP[16], aN[16];
            for (int i = lb; i < le; i++) {
                const unsigned e = __ldg(&g_list[i]);
                const int s = (int)(e >> 16);
                if (s != curS) {
                    if (curS >= 0) {
                        #pragma unroll
                        for (int r = 0; r < 16; r++)
                            atomicAdd(&dy[r * SB + curS], aP[r] - aN[r]);
                        if (curSurf) {
                            #pragma unroll
                            for (int r = 0; r < 16; r++) atomicAdd(&lossTot[r], aN[r]);
                        }
                    }
                    curS = s;
                    curSurf = (unsigned)(s - s0) < NSS;
                    #pragma unroll
                    for (int r = 0; r < 16; r++) { aP[r] = 0.f; aN[r] = 0.f; }
                }
                const int idx = (int)(e & 0x7FFFu) * 4;
                const bool neg = (e & 0x8000u) != 0;
                #pragma unroll
                for (int q = 0; q < 4; q++) {
                    float4 t = terms[idx + q];
                    if (neg) { aN[4*q+0] += t.x; aN[4*q+1] += t.y; aN[4*q+2] += t.z; aN[4*q+3] += t.w; }
                    else     { aP[4*q+0] += t.x; aP[4*q+1] += t.y; aP[4*q+2] += t.z; aP[4*q+3] += t.w; }
                }
            }
            if (curS >= 0) {
                #pragma unroll
                for (int r = 0; r < 16; r++)
                    atomicAdd(&dy[r * SB + curS], aP[r] - aN[r]);
                if (curSurf) {
                    #pragma unroll
                    for (int r = 0; r < 16; r++) atomicAdd(&lossTot[r], aN[r]);
                }
            }
        }
        __syncthreads();
    }

    // ---- reductions: per row {sumNetSurf, ySurfTot, yMantTot}; loss in lossTot ----
    float vals[48];
    #pragma unroll
    for (int v = 0; v < 48; v++) vals[v] = 0.f;
    if (tid < 256) {
        int s = s0 + tid;
        #pragma unroll
        for (int r = 0; r < 16; r++) vals[r] = dy[r * SB + s];
        #pragma unroll
        for (int q = 0; q < 4; q++) {
            float4 yv = yq[q * SB + s];
            vals[16 + 4*q + 0] = yv.x; vals[16 + 4*q + 1] = yv.y;
            vals[16 + 4*q + 2] = yv.z; vals[16 + 4*q + 3] = yv.w;
        }
    } else {
        int s = m0 + (tid - 256);
        #pragma unroll
        for (int q = 0; q < 4; q++) {
            float4 yv = yq[q * SB + s];
            vals[32 + 4*q + 0] = yv.x; vals[32 + 4*q + 1] = yv.y;
            vals[32 + 4*q + 2] = yv.z; vals[32 + 4*q + 3] = yv.w;
        }
    }
    {
        int w = tid >> 5;
        #pragma unroll
        for (int v = 0; v < 48; v++) {
            float x = warp_red(vals[v]);
            if (lane == 0) red[v][w] = x;
        }
        __syncthreads();
        if (tid < 48) {
            float s = 0.f;
            #pragma unroll
            for (int i = 0; i < NT / 32; i++) s += red[tid][i];
            tot[tid] = s;
        }
        __syncthreads();
    }

    float ks2m[16], km2s[16];
    #pragma unroll
    for (int r = 0; r < 16; r++) {
        float loss = lossTot[r];
        float gain = tot[r] + loss;                 // gain = sumNetSurf + loss
        ks2m[r] = gain / (tot[16 + r] + 1e-10f);
        km2s[r] = loss / (tot[32 + r] + 1e-10f);
    }

    // ---- epilogue: surface<->mantle transfer + write out (2 species/thread) ----
    #pragma unroll
    for (int gsp = 0; gsp < 2; gsp++) {
        int s = tid + gsp * NT;
        float dv[16], yv[16];
        #pragma unroll
        for (int r = 0; r < 16; r++) dv[r] = dy[r * SB + s];
        #pragma unroll
        for (int q = 0; q < 4; q++) {
            float4 t = yq[q * SB + s];
            yv[4*q+0] = t.x; yv[4*q+1] = t.y; yv[4*q+2] = t.z; yv[4*q+3] = t.w;
        }
        unsigned ds = (unsigned)(s - s0), dm = (unsigned)(s - m0);
        if (ds < NSS) {
            float pm[16];
            #pragma unroll
            for (int q = 0; q < 4; q++) {
                float4 t = yq[q * SB + (m0 + (int)ds)];
                pm[4*q+0] = t.x; pm[4*q+1] = t.y; pm[4*q+2] = t.z; pm[4*q+3] = t.w;
            }
            #pragma unroll
            for (int r = 0; r < 16; r++) dv[r] += km2s[r] * pm[r] - ks2m[r] * yv[r];
        } else if (dm < NSS) {
            float ps[16];
            #pragma unroll
            for (int q = 0; q < 4; q++) {
                float4 t = yq[q * SB + (s0 + (int)dm)];
                ps[4*q+0] = t.x; ps[4*q+1] = t.y; ps[4*q+2] = t.z; ps[4*q+3] = t.w;
            }
            #pragma unroll
            for (int r = 0; r < 16; r++) dv[r] += ks2m[r] * ps[r] - km2s[r] * yv[r];
        }
        #pragma unroll
        for (int r = 0; r < 16; r++)
            out[(size_t)(b0 + r) * SB + s] = dv[r];
    }
}

extern "C" void kernel_launch(void* const* d_in, const int* in_sizes, int n_in,
                              void* d_out, int out_size) {
    const float* t_in    = (const float*)d_in[0];
    const float* y_in    = (const float*)d_in[1];
    const float* den_gas = (const float*)d_in[2];
    const float* a1      = (const float*)d_in[3];
    const float* g1      = (const float*)d_in[4];
    const float* a2      = (const float*)d_in[5];
    const float* g2      = (const float*)d_in[6];
    const int*   r11     = (const int*)d_in[7];
    const int*   p1      = (const int*)d_in[8];
    const int*   r12     = (const int*)d_in[9];
    const int*   r22     = (const int*)d_in[10];
    const int*   p2      = (const int*)d_in[11];
    const int*   inds_s  = (const int*)d_in[12];
    const int*   inds_m  = (const int*)d_in[13];
    float*       out     = (float*)d_out;

    const int B = in_sizes[0];

    cudaFuncSetAttribute(three_phase_rhs,
                         cudaFuncAttributeMaxDynamicSharedMemorySize, SMEM_BYTES);

    k_count<<<(NROLES + 255) / 256, 256>>>(p1, r11, p2, r12, r22);
    k_scan <<<1, 1024>>>();
    k_fill <<<(NROLES + 255) / 256, 256>>>(p1, r11, p2, r12, r22);

    three_phase_rhs<<<B / ROWS, NT, SMEM_BYTES>>>(
        t_in, y_in, den_gas, a1, g1, a2, g2,
        r11, r12, r22, inds_s, inds_m, out);
}

// round 12
// speedup vs baseline: 7.7506x; 7.7506x over previous
#include <cuda_runtime.h>

// ---- problem constants ----
#define SB      1024
#define N1      8192
#define N2      16384
#define NTERMS  (N1 + N2)            // 24576
#define NC      10                   // chunks
#define CHUNK   2464                 // NC*CHUNK >= NTERMS
#define NSS     256
#define NT      512
#define ROWS    8
#define SPT     (SB / NT)            // 2 species per thread
#define NCTR    (SB * NC)            // 10240 sublists (species x chunk)
#define NROLES  (2 * N1 + 3 * N2)    // 65536
#define LIST_CAP 75784               // NROLES + NCTR + 8
#define DUMMY16  0x09A009A0u         // two packed dummy indices (=CHUNK=0x9A0)

// ---- persistent scratch (rebuilt every launch; structure is input-constant) ----
__device__ int g_cnt[2 * NCTR];
__device__ int g_curG[NCTR];
__device__ int g_curL[NCTR];
__device__ int g_off[NCTR + 1];      // padded sublist starts (even)
__device__ int g_mid[NCTR];          // gain/loss boundary
__device__ __align__(16) unsigned short g_list[LIST_CAP];

// dynamic smem: tlo f4[CHUNK+1] | thi f4[CHUNK+1] | ylo f4[SB] | yhi f4[SB]
#define SMEM_BYTES ((2 * (CHUNK + 1) + 2 * SB) * 16)   // 111,648 B -> 2 CTAs/SM

__inline__ __device__ float warp_red(float v) {
    #pragma unroll
    for (int o = 16; o > 0; o >>= 1) v += __shfl_xor_sync(0xFFFFFFFFu, v, o);
    return v;
}

// ---------- build kernels (3 launches) ----------
__device__ __forceinline__ void decode_role(
    int id, const int* p1, const int* r11, const int* p2,
    const int* r12, const int* r22, int& term, int& s, int& loss)
{
    if (id < N1)                 { term = id;                  s = __ldg(p1  + id);          loss = 0; }
    else if (id < 2 * N1)        { term = id - N1;             s = __ldg(r11 + id - N1);     loss = 1; }
    else if (id < 2 * N1 + N2)   { int j = id - 2 * N1;        term = N1 + j; s = __ldg(p2  + j); loss = 0; }
    else if (id < 2 * N1 + 2*N2) { int j = id - 2 * N1 - N2;   term = N1 + j; s = __ldg(r12 + j); loss = 1; }
    else                         { int j = id - 2 * N1 - 2*N2; term = N1 + j; s = __ldg(r22 + j); loss = 1; }
}

__global__ void k_count(const int* __restrict__ p1, const int* __restrict__ r11,
                        const int* __restrict__ p2, const int* __restrict__ r12,
                        const int* __restrict__ r22) {
    int id = blockIdx.x * blockDim.x + threadIdx.x;
    if (id >= NROLES) return;
    int term, s, loss;
    decode_role(id, p1, r11, p2, r12, r22, term, s, loss);
    int c = term / CHUNK;
    atomicAdd(&g_cnt[2 * (s * NC + c) + loss], 1);
}

__global__ void k_scan() {   // 1 CTA, 1024 threads: scan + cursors + re-zero + prefill
    __shared__ int sh[1024];
    int t = threadIdx.x;
    int gc[NC], lc[NC]; int tsum = 0;
    #pragma unroll
    for (int u = 0; u < NC; u++) {
        int sub = t * NC + u;
        gc[u] = g_cnt[2 * sub];
        lc[u] = g_cnt[2 * sub + 1];
        tsum += (gc[u] + lc[u] + 1) & ~1;
    }
    sh[t] = tsum;
    __syncthreads();
    for (int o = 1; o < 1024; o <<= 1) {
        int x = (t >= o) ? sh[t - o] : 0;
        __syncthreads();
        sh[t] += x;
        __syncthreads();
    }
    int excl = sh[t] - tsum;
    #pragma unroll
    for (int u = 0; u < NC; u++) {
        int sub = t * NC + u;
        g_off[sub]  = excl;
        g_curG[sub] = excl;
        g_mid[sub]  = excl + gc[u];
        g_curL[sub] = excl + gc[u];
        excl += (gc[u] + lc[u] + 1) & ~1;
        g_cnt[2 * sub] = 0;
        g_cnt[2 * sub + 1] = 0;
    }
    if (t == 1023) g_off[NCTR] = sh[1023];
    uint4 dv = make_uint4(DUMMY16, DUMMY16, DUMMY16, DUMMY16);
    uint4* lp = (uint4*)g_list;
    for (int i = t; i < LIST_CAP / 8; i += 1024) lp[i] = dv;
}

__global__ void k_fill(const int* __restrict__ p1, const int* __restrict__ r11,
                       const int* __restrict__ p2, const int* __restrict__ r12,
                       const int* __restrict__ r22) {
    int id = blockIdx.x * blockDim.x + threadIdx.x;
    if (id >= NROLES) return;
    int term, s, loss;
    decode_role(id, p1, r11, p2, r12, r22, term, s, loss);
    int c = term / CHUNK;
    int sub = s * NC + c;
    int pos = loss ? atomicAdd(&g_curL[sub], 1) : atomicAdd(&g_curG[sub], 1);
    g_list[pos] = (unsigned short)(term - c * CHUNK);
}

// ---------- phase-2 entry-pair processor ----------
__device__ __forceinline__ void proc2(
    unsigned w, int pos, int mid, bool surf,
    const float4* __restrict__ tlo, const float4* __restrict__ thi,
    float (&net)[ROWS], float (&ng)[ROWS])
{
    const int e0 = (int)(w & 0xFFFFu), e1 = (int)(w >> 16);
    float4 l0 = tlo[e0], h0 = thi[e0];
    float4 l1 = tlo[e1], h1 = thi[e1];
    const float sg0 = (pos     < mid) ? 1.f : -1.f;
    const float sg1 = (pos + 1 < mid) ? 1.f : -1.f;
    net[0] = fmaf(sg0, l0.x, net[0]); net[1] = fmaf(sg0, l0.y, net[1]);
    net[2] = fmaf(sg0, l0.z, net[2]); net[3] = fmaf(sg0, l0.w, net[3]);
    net[4] = fmaf(sg0, h0.x, net[4]); net[5] = fmaf(sg0, h0.y, net[5]);
    net[6] = fmaf(sg0, h0.z, net[6]); net[7] = fmaf(sg0, h0.w, net[7]);
    net[0] = fmaf(sg1, l1.x, net[0]); net[1] = fmaf(sg1, l1.y, net[1]);
    net[2] = fmaf(sg1, l1.z, net[2]); net[3] = fmaf(sg1, l1.w, net[3]);
    net[4] = fmaf(sg1, h1.x, net[4]); net[5] = fmaf(sg1, h1.y, net[5]);
    net[6] = fmaf(sg1, h1.z, net[6]); net[7] = fmaf(sg1, h1.w, net[7]);
    if (surf) {                        // warp-uniform
        if (pos >= mid) {
            ng[0] += l0.x; ng[1] += l0.y; ng[2] += l0.z; ng[3] += l0.w;
            ng[4] += h0.x; ng[5] += h0.y; ng[6] += h0.z; ng[7] += h0.w;
        }
        if (pos + 1 >= mid) {
            ng[0] += l1.x; ng[1] += l1.y; ng[2] += l1.z; ng[3] += l1.w;
            ng[4] += h1.x; ng[5] += h1.y; ng[6] += h1.z; ng[7] += h1.w;
        }
    }
}

// ---------- main kernel: 8 rows/CTA, NT=512, 2 CTAs/SM ----------
__global__ __launch_bounds__(NT, 2) void three_phase_rhs(
    const float* __restrict__ t_in, const float* __restrict__ y_in,
    const float* __restrict__ den_gas,
    const float* __restrict__ a1, const float* __restrict__ g1,
    const float* __restrict__ a2, const float* __restrict__ g2,
    const int* __restrict__ r11, const int* __restrict__ r12,
    const int* __restrict__ r22,
    const int* __restrict__ inds_s, const int* __restrict__ inds_m,
    float* __restrict__ out)
{
    extern __shared__ float4 smem4[];
    float4* tlo = smem4;                     // rows 0-3; [CHUNK] is zero dummy
    float4* thi = tlo + (CHUNK + 1);         // rows 4-7
    float4* ylo = thi + (CHUNK + 1);         // y rows 0-3
    float4* yhi = ylo + SB;                  // y rows 4-7
    __shared__ float red[32][NT / 32];
    __shared__ float tot[32];
    __shared__ float sh_pr[16];              // nI[0..7] | c2[0..7]

    const int tid = threadIdx.x;
    const int b0 = blockIdx.x * ROWS;

    {
        const float* yr = y_in + (size_t)b0 * SB;
        for (int i = tid; i < SB; i += NT) {
            ylo[i] = make_float4(yr[i], yr[i + SB], yr[i + 2 * SB], yr[i + 3 * SB]);
            yhi[i] = make_float4(yr[i + 4 * SB], yr[i + 5 * SB], yr[i + 6 * SB], yr[i + 7 * SB]);
        }
    }
    if (tid == 0) {
        tlo[CHUNK] = make_float4(0.f, 0.f, 0.f, 0.f);
        thi[CHUNK] = make_float4(0.f, 0.f, 0.f, 0.f);
    }
    if (tid < ROWS) {     // per-row params -> shared (register relief)
        float T = 10.0f + 5.0f / (1.0f + __expf(-__ldg(t_in + b0 + tid)));
        sh_pr[tid] = -1.0f / T;
        sh_pr[tid + 8] = sqrtf(T * (1.0f / 300.0f)) * __ldg(den_gas + b0 + tid);
    }
    const int s0 = __ldg(&inds_s[0]), m0 = __ldg(&inds_m[0]);

    bool isSurf[SPT], isMant[SPT];
    #pragma unroll
    for (int gsp = 0; gsp < SPT; gsp++) {
        int s = tid + gsp * NT;
        isSurf[gsp] = (unsigned)(s - s0) < NSS;
        isMant[gsp] = (unsigned)(s - m0) < NSS;
    }
    __syncthreads();

    float net[SPT][ROWS];
    float ng[ROWS];
    #pragma unroll
    for (int g = 0; g < SPT; g++)
        #pragma unroll
        for (int r = 0; r < ROWS; r++) net[g][r] = 0.f;
    #pragma unroll
    for (int r = 0; r < ROWS; r++) ng[r] = 0.f;

    for (int c = 0; c < NC; c++) {
        const int base = c * CHUNK;
        const int clen = min(CHUNK, NTERMS - base);

        // ---- phase 1: terms for this chunk (nI/c2 reloaded -> short live range) ----
        {
            float nI[ROWS], c2[ROWS];
            #pragma unroll
            for (int r = 0; r < ROWS; r++) { nI[r] = sh_pr[r]; c2[r] = sh_pr[r + 8]; }
            for (int jj = tid; jj < clen; jj += NT) {
                int j = base + jj;
                float4 lo, hi;
                if (j < N1) {
                    float a = __ldg(a1 + j), g = __ldg(g1 + j);
                    int   rr = __ldg(r11 + j);
                    float4 ya = ylo[rr], yb = yhi[rr];
                    lo.x = a * __expf(g * nI[0]) * ya.x;
                    lo.y = a * __expf(g * nI[1]) * ya.y;
                    lo.z = a * __expf(g * nI[2]) * ya.z;
                    lo.w = a * __expf(g * nI[3]) * ya.w;
                    hi.x = a * __expf(g * nI[4]) * yb.x;
                    hi.y = a * __expf(g * nI[5]) * yb.y;
                    hi.z = a * __expf(g * nI[6]) * yb.z;
                    hi.w = a * __expf(g * nI[7]) * yb.w;
                } else {
                    int j2 = j - N1;
                    float a = __ldg(a2 + j2), g = __ldg(g2 + j2);
                    int  rA = __ldg(r12 + j2), rB = __ldg(r22 + j2);
                    float4 yaA = ylo[rA], yaB = ylo[rB];
                    float4 ybA = yhi[rA], ybB = yhi[rB];
                    lo.x = a * c2[0] * __expf(g * nI[0]) * yaA.x * yaB.x;
                    lo.y = a * c2[1] * __expf(g * nI[1]) * yaA.y * yaB.y;
                    lo.z = a * c2[2] * __expf(g * nI[2]) * yaA.z * yaB.z;
                    lo.w = a * c2[3] * __expf(g * nI[3]) * yaA.w * yaB.w;
                    hi.x = a * c2[4] * __expf(g * nI[4]) * ybA.x * ybB.x;
                    hi.y = a * c2[5] * __expf(g * nI[5]) * ybA.y * ybB.y;
                    hi.z = a * c2[6] * __expf(g * nI[6]) * ybA.z * ybB.z;
                    hi.w = a * c2[7] * __expf(g * nI[7]) * ybA.w * ybB.w;
                }
                tlo[jj] = lo;
                thi[jj] = hi;
            }
        }
        __syncthreads();

        // ---- phase 2: gather; MLP-4 batched list loads (8 entries per iter) ----
        #pragma unroll
        for (int gsp = 0; gsp < SPT; gsp++) {
            const int s = tid + gsp * NT;
            const int ob = s * NC + c;
            const int beg = __ldg(&g_off[ob]);
            const int mid = __ldg(&g_mid[ob]);
            const int end = __ldg(&g_off[ob + 1]);
            const bool surf = isSurf[gsp];
            for (int i = beg; i < end; i += 8) {
                const unsigned w0 = *(const unsigned*)(g_list + i);
                const unsigned w1 = (i + 2 < end) ? *(const unsigned*)(g_list + i + 2) : DUMMY16;
                const unsigned w2 = (i + 4 < end) ? *(const unsigned*)(g_list + i + 4) : DUMMY16;
                const unsigned w3 = (i + 6 < end) ? *(const unsigned*)(g_list + i + 6) : DUMMY16;
                proc2(w0, i,     mid, surf, tlo, thi, net[gsp], ng);
                proc2(w1, i + 2, mid, surf, tlo, thi, net[gsp], ng);
                proc2(w2, i + 4, mid, surf, tlo, thi, net[gsp], ng);
                proc2(w3, i + 6, mid, surf, tlo, thi, net[gsp], ng);
            }
        }
        __syncthreads();
    }

    // ---- reductions: per row {gain, loss, ysurf, ymant} ----
    float vals[32];
    #pragma unroll
    for (int v = 0; v < 32; v++) vals[v] = 0.f;
    #pragma unroll
    for (int gsp = 0; gsp < SPT; gsp++) {
        int s = tid + gsp * NT;
        float4 ya = ylo[s], yb = yhi[s];
        float yr[ROWS] = { ya.x, ya.y, ya.z, ya.w, yb.x, yb.y, yb.z, yb.w };
        if (isSurf[gsp]) {
            #pragma unroll
            for (int r = 0; r < ROWS; r++) {
                vals[4 * r + 0] += net[gsp][r] + ng[r];
                vals[4 * r + 1] += ng[r];
                vals[4 * r + 2] += yr[r];
            }
        } else if (isMant[gsp]) {
            #pragma unroll
            for (int r = 0; r < ROWS; r++) vals[4 * r + 3] += yr[r];
        }
    }
    {
        int lane = tid & 31, w = tid >> 5;
        #pragma unroll
        for (int v = 0; v < 32; v++) {
            float x = warp_red(vals[v]);
            if (lane == 0) red[v][w] = x;
        }
        __syncthreads();
        if (tid < 32) {
            float s = 0.f;
            #pragma unroll
            for (int i = 0; i < NT / 32; i++) s += red[tid][i];
            tot[tid] = s;
        }
        __syncthreads();
    }

    float ks2m[ROWS], km2s[ROWS];
    #pragma unroll
    for (int r = 0; r < ROWS; r++) {
        ks2m[r] = tot[4 * r + 0] / (tot[4 * r + 2] + 1e-10f);
        km2s[r] = tot[4 * r + 1] / (tot[4 * r + 3] + 1e-10f);
    }

    // ---- epilogue: surface<->mantle transfer + write out ----
    #pragma unroll
    for (int gsp = 0; gsp < SPT; gsp++) {
        int s = tid + gsp * NT;
        float dy[ROWS];
        #pragma unroll
        for (int r = 0; r < ROWS; r++) dy[r] = net[gsp][r];
        unsigned ds = (unsigned)(s - s0), dm = (unsigned)(s - m0);
        if (ds < NSS) {
            float4 ma = ylo[m0 + ds], mb = yhi[m0 + ds];
            float4 sa = ylo[s],       sb = yhi[s];
            float ymr[ROWS] = { ma.x, ma.y, ma.z, ma.w, mb.x, mb.y, mb.z, mb.w };
            float ysr[ROWS] = { sa.x, sa.y, sa.z, sa.w, sb.x, sb.y, sb.z, sb.w };
            #pragma unroll
            for (int r = 0; r < ROWS; r++) dy[r] += km2s[r] * ymr[r] - ks2m[r] * ysr[r];
        } else if (dm < NSS) {
            float4 sa = ylo[s0 + dm], sb = yhi[s0 + dm];
            float4 ma = ylo[s],       mb = yhi[s];
            float ysr[ROWS] = { sa.x, sa.y, sa.z, sa.w, sb.x, sb.y, sb.z, sb.w };
            float ymr[ROWS] = { ma.x, ma.y, ma.z, ma.w, mb.x, mb.y, mb.z, mb.w };
            #pragma unroll
            for (int r = 0; r < ROWS; r++) dy[r] += ks2m[r] * ysr[r] - km2s[r] * ymr[r];
        }
        #pragma unroll
        for (int r = 0; r < ROWS; r++)
            out[(size_t)(b0 + r) * SB + s] = dy[r];
    }
}

extern "C" void kernel_launch(void* const* d_in, const int* in_sizes, int n_in,
                              void* d_out, int out_size) {
    const float* t_in    = (const float*)d_in[0];
    const float* y_in    = (const float*)d_in[1];
    const float* den_gas = (const float*)d_in[2];
    const float* a1      = (const float*)d_in[3];
    const float* g1      = (const float*)d_in[4];
    const float* a2      = (const float*)d_in[5];
    const float* g2      = (const float*)d_in[6];
    const int*   r11     = (const int*)d_in[7];
    const int*   p1      = (const int*)d_in[8];
    const int*   r12     = (const int*)d_in[9];
    const int*   r22     = (const int*)d_in[10];
    const int*   p2      = (const int*)d_in[11];
    const int*   inds_s  = (const int*)d_in[12];
    const int*   inds_m  = (const int*)d_in[13];
    float*       out     = (float*)d_out;

    const int B = in_sizes[0];

    cudaFuncSetAttribute(three_phase_rhs,
                         cudaFuncAttributeMaxDynamicSharedMemorySize, SMEM_BYTES);

    k_count<<<(NROLES + 255) / 256, 256>>>(p1, r11, p2, r12, r22);
    k_scan <<<1, 1024>>>();
    k_fill <<<(NROLES + 255) / 256, 256>>>(p1, r11, p2, r12, r22);

    three_phase_rhs<<<B / ROWS, NT, SMEM_BYTES>>>(
        t_in, y_in, den_gas, a1, g1, a2, g2,
        r11, r12, r22, inds_s, inds_m, out);
}

// round 14
// speedup vs baseline: 10.7301x; 1.3844x over previous
#include <cuda_runtime.h>

// ---- problem constants ----
#define SB      1024
#define N1      8192
#define N2      16384
#define NTERMS  (N1 + N2)            // 24576
#define NC      12                   // chunks
#define CHUNK   2048                 // NC*CHUNK == NTERMS exactly; power of 2
#define CSHIFT  11
#define NSS     256
#define NT      512
#define ROWS    8
#define SPT     (SB / NT)            // 2 species per thread
#define NCTR    (NC * SB)            // 12288 sublists, chunk-major: sub = c*SB + s
#define NROLES  (2 * N1 + 3 * N2)    // 65536
#define LIST_CAP 77936               // 65536 + pads + alignment + slack
#define LCAP    8192                 // smem list buffer entries (worst slice ~6700)

// ---- persistent scratch (rebuilt every launch; structure is input-constant) ----
__device__ int g_cnt[2 * NCTR];      // (sublist, gain/loss) counts — static zero init
__device__ int g_curG[NCTR];
__device__ int g_curL[NCTR];
__device__ int g_off[NCTR + 1];      // padded sublist starts; chunk slices 8-aligned
__device__ int g_mid[NCTR];          // gain/loss boundary
__device__ __align__(16) unsigned short g_list[LIST_CAP];

// dynamic smem: tlo f4[CHUNK+1] | thi f4[CHUNK+1] | ylo f4[SB] | yhi f4[SB] | lbuf u16[LCAP]
// (reduction scratch red/tot aliases lbuf — lbuf dead by reduction time)
#define SMEM_BYTES ((2 * (CHUNK + 1) + 2 * SB) * 16 + LCAP * 2)   // 114,720 B

__inline__ __device__ float warp_red(float v) {
    #pragma unroll
    for (int o = 16; o > 0; o >>= 1) v += __shfl_xor_sync(0xFFFFFFFFu, v, o);
    return v;
}

// ---------- build kernels (3 launches) ----------
__device__ __forceinline__ void decode_role(
    int id, const int* p1, const int* r11, const int* p2,
    const int* r12, const int* r22, int& term, int& s, int& loss)
{
    if (id < N1)                 { term = id;                  s = __ldg(p1  + id);          loss = 0; }
    else if (id < 2 * N1)        { term = id - N1;             s = __ldg(r11 + id - N1);     loss = 1; }
    else if (id < 2 * N1 + N2)   { int j = id - 2 * N1;        term = N1 + j; s = __ldg(p2  + j); loss = 0; }
    else if (id < 2 * N1 + 2*N2) { int j = id - 2 * N1 - N2;   term = N1 + j; s = __ldg(r12 + j); loss = 1; }
    else                         { int j = id - 2 * N1 - 2*N2; term = N1 + j; s = __ldg(r22 + j); loss = 1; }
}

__global__ void k_count(const int* __restrict__ p1, const int* __restrict__ r11,
                        const int* __restrict__ p2, const int* __restrict__ r12,
                        const int* __restrict__ r22) {
    int id = blockIdx.x * blockDim.x + threadIdx.x;
    if (id >= NROLES) return;
    int term, s, loss;
    decode_role(id, p1, r11, p2, r12, r22, term, s, loss);
    int sub = ((term >> CSHIFT) << 10) + s;      // c*SB + s
    atomicAdd(&g_cnt[2 * sub + loss], 1);
}

__global__ void k_scan() {   // 1 CTA, 1024 threads; per-chunk shuffle scan
    __shared__ int wsum[32];
    __shared__ int chunkBase;
    const int t = threadIdx.x, lane = t & 31, w = t >> 5;
    if (t == 0) chunkBase = 0;
    __syncthreads();
    for (int c = 0; c < NC; c++) {
        const int sub = c * SB + t;
        const int gcv = g_cnt[2 * sub];
        const int lcv = g_cnt[2 * sub + 1];
        const int pcv = (gcv + lcv + 1) & ~1;          // pad sublist to 2
        // two-level inclusive scan of pcv
        int v = pcv;
        #pragma unroll
        for (int o = 1; o < 32; o <<= 1) {
            int x = __shfl_up_sync(0xFFFFFFFFu, v, o);
            if (lane >= o) v += x;
        }
        if (lane == 31) wsum[w] = v;
        __syncthreads();
        if (w == 0) {
            int wv = wsum[lane];
            #pragma unroll
            for (int o = 1; o < 32; o <<= 1) {
                int x = __shfl_up_sync(0xFFFFFFFFu, wv, o);
                if (lane >= o) wv += x;
            }
            wsum[lane] = wv;
        }
        __syncthreads();
        const int excl = chunkBase + (w ? wsum[w - 1] : 0) + v - pcv;
        g_off[sub]  = excl;
        g_curG[sub] = excl;
        g_mid[sub]  = excl + gcv;
        g_curL[sub] = excl + gcv;
        if ((gcv + lcv) < pcv)                          // odd count -> one dummy slot
            g_list[excl + gcv + lcv] = (unsigned short)CHUNK;
        g_cnt[2 * sub] = 0;                             // re-zero for next launch
        g_cnt[2 * sub + 1] = 0;
        __syncthreads();
        if (t == 1023) {
            int trueEnd = excl + pcv;                   // chunk's true slice end
            int aligned = (trueEnd + 7) & ~7;
            for (int p = trueEnd; p < aligned; p++)     // FIX: fill alignment gap
                g_list[p] = (unsigned short)CHUNK;
            chunkBase = aligned;
        }
        __syncthreads();
    }
    if (t == 0) g_off[NCTR] = chunkBase;
}

__global__ void k_fill(const int* __restrict__ p1, const int* __restrict__ r11,
                       const int* __restrict__ p2, const int* __restrict__ r12,
                       const int* __restrict__ r22) {
    int id = blockIdx.x * blockDim.x + threadIdx.x;
    if (id >= NROLES) return;
    int term, s, loss;
    decode_role(id, p1, r11, p2, r12, r22, term, s, loss);
    int sub = ((term >> CSHIFT) << 10) + s;
    int pos = loss ? atomicAdd(&g_curL[sub], 1) : atomicAdd(&g_curG[sub], 1);
    g_list[pos] = (unsigned short)(term & (CHUNK - 1));
}

// ---------- main kernel: 8 rows/CTA, NT=512, 2 CTAs/SM, smem-staged list ----------
__global__ __launch_bounds__(NT, 2) void three_phase_rhs(
    const float* __restrict__ t_in, const float* __restrict__ y_in,
    const float* __restrict__ den_gas,
    const float* __restrict__ a1, const float* __restrict__ g1,
    const float* __restrict__ a2, const float* __restrict__ g2,
    const int* __restrict__ r11, const int* __restrict__ r12,
    const int* __restrict__ r22,
    const int* __restrict__ inds_s, const int* __restrict__ inds_m,
    float* __restrict__ out)
{
    extern __shared__ float4 smem4[];
    float4* tlo = smem4;                          // rows 0-3; [CHUNK] is zero dummy
    float4* thi = tlo + (CHUNK + 1);              // rows 4-7
    float4* ylo = thi + (CHUNK + 1);              // y rows 0-3
    float4* yhi = ylo + SB;                       // y rows 4-7
    unsigned short* lbuf = (unsigned short*)(yhi + SB);   // [LCAP]
    // reduction scratch aliases lbuf (live only after the chunk loop)
    float (*red)[NT / 32] = (float (*)[NT / 32])lbuf;
    float* tot = (float*)lbuf + 32 * (NT / 32);
    __shared__ float sh_pr[16];                   // nI[0..7] | c2[0..7]

    const int tid = threadIdx.x;
    const int b0 = blockIdx.x * ROWS;

    {
        const float* yr = y_in + (size_t)b0 * SB;
        for (int i = tid; i < SB; i += NT) {
            ylo[i] = make_float4(yr[i], yr[i + SB], yr[i + 2 * SB], yr[i + 3 * SB]);
            yhi[i] = make_float4(yr[i + 4 * SB], yr[i + 5 * SB], yr[i + 6 * SB], yr[i + 7 * SB]);
        }
    }
    if (tid == 0) {
        tlo[CHUNK] = make_float4(0.f, 0.f, 0.f, 0.f);
        thi[CHUNK] = make_float4(0.f, 0.f, 0.f, 0.f);
    }
    if (tid < ROWS) {                             // per-row params -> shared
        float T = 10.0f + 5.0f / (1.0f + __expf(-__ldg(t_in + b0 + tid)));
        sh_pr[tid] = -1.0f / T;
        sh_pr[tid + 8] = sqrtf(T * (1.0f / 300.0f)) * __ldg(den_gas + b0 + tid);
    }
    const int s0 = __ldg(&inds_s[0]), m0 = __ldg(&inds_m[0]);

    bool isSurf[SPT], isMant[SPT];
    #pragma unroll
    for (int gsp = 0; gsp < SPT; gsp++) {
        int s = tid + gsp * NT;
        isSurf[gsp] = (unsigned)(s - s0) < NSS;
        isMant[gsp] = (unsigned)(s - m0) < NSS;
    }
    __syncthreads();

    float net[SPT][ROWS];
    float ng[ROWS];
    #pragma unroll
    for (int g = 0; g < SPT; g++)
        #pragma unroll
        for (int r = 0; r < ROWS; r++) net[g][r] = 0.f;
    #pragma unroll
    for (int r = 0; r < ROWS; r++) ng[r] = 0.f;

    for (int c = 0; c < NC; c++) {
        const int base = c * CHUNK;

        // prefetch this chunk's sublist offsets (L2 latency hides under phase 1)
        int beg[SPT], mid[SPT], end[SPT];
        #pragma unroll
        for (int gsp = 0; gsp < SPT; gsp++) {
            const int ob = c * SB + tid + gsp * NT;
            beg[gsp] = __ldg(&g_off[ob]);
            mid[gsp] = __ldg(&g_mid[ob]);
            end[gsp] = __ldg(&g_off[ob + 1]);
        }
        const int sliceBeg = __ldg(&g_off[c * SB]);           // 8-aligned
        const int sliceEnd = __ldg(&g_off[(c + 1) * SB]);     // 8-aligned

        // stage this chunk's list slice into shared (overlaps phase-1 compute)
        {
            const int n16 = min(sliceEnd - sliceBeg, LCAP) >> 3;
            const uint4* src = (const uint4*)(g_list + sliceBeg);
            uint4* dst = (uint4*)lbuf;
            for (int k = tid; k < n16; k += NT) dst[k] = src[k];
        }

        // ---- phase 1: terms for this chunk ----
        {
            float nI[ROWS], c2[ROWS];
            #pragma unroll
            for (int r = 0; r < ROWS; r++) { nI[r] = sh_pr[r]; c2[r] = sh_pr[r + 8]; }
            for (int jj = tid; jj < CHUNK; jj += NT) {
                int j = base + jj;
                float4 lo, hi;
                if (j < N1) {
                    float a = __ldg(a1 + j), g = __ldg(g1 + j);
                    int   rr = __ldg(r11 + j);
                    float4 ya = ylo[rr], yb = yhi[rr];
                    lo.x = a * __expf(g * nI[0]) * ya.x;
                    lo.y = a * __expf(g * nI[1]) * ya.y;
                    lo.z = a * __expf(g * nI[2]) * ya.z;
                    lo.w = a * __expf(g * nI[3]) * ya.w;
                    hi.x = a * __expf(g * nI[4]) * yb.x;
                    hi.y = a * __expf(g * nI[5]) * yb.y;
                    hi.z = a * __expf(g * nI[6]) * yb.z;
                    hi.w = a * __expf(g * nI[7]) * yb.w;
                } else {
                    int j2 = j - N1;
                    float a = __ldg(a2 + j2), g = __ldg(g2 + j2);
                    int  rA = __ldg(r12 + j2), rB = __ldg(r22 + j2);
                    float4 yaA = ylo[rA], yaB = ylo[rB];
                    float4 ybA = yhi[rA], ybB = yhi[rB];
                    lo.x = a * c2[0] * __expf(g * nI[0]) * yaA.x * yaB.x;
                    lo.y = a * c2[1] * __expf(g * nI[1]) * yaA.y * yaB.y;
                    lo.z = a * c2[2] * __expf(g * nI[2]) * yaA.z * yaB.z;
                    lo.w = a * c2[3] * __expf(g * nI[3]) * yaA.w * yaB.w;
                    hi.x = a * c2[4] * __expf(g * nI[4]) * ybA.x * ybB.x;
                    hi.y = a * c2[5] * __expf(g * nI[5]) * ybA.y * ybB.y;
                    hi.z = a * c2[6] * __expf(g * nI[6]) * ybA.z * ybB.z;
                    hi.w = a * c2[7] * __expf(g * nI[7]) * ybA.w * ybB.w;
                }
                tlo[jj] = lo;
                thi[jj] = hi;
            }
        }
        __syncthreads();   // terms + lbuf both ready

        // ---- phase 2: gather from smem-staged list ----
        #pragma unroll
        for (int gsp = 0; gsp < SPT; gsp++) {
            const bool surf = isSurf[gsp];
            const int m = mid[gsp], e = end[gsp];
            for (int i = beg[gsp]; i < e; i += 2) {
                const int li = i - sliceBeg;
                const unsigned w = (li < LCAP) ? *(const unsigned*)(lbuf + li)
                                               : *(const unsigned*)(g_list + i);
                const int e0 = (int)(w & 0xFFFFu), e1 = (int)(w >> 16);
                float4 l0 = tlo[e0], h0 = thi[e0];
                float4 l1 = tlo[e1], h1 = thi[e1];
                const float sg0 = (i     < m) ? 1.f : -1.f;
                const float sg1 = (i + 1 < m) ? 1.f : -1.f;
                net[gsp][0] = fmaf(sg0, l0.x, net[gsp][0]);
                net[gsp][1] = fmaf(sg0, l0.y, net[gsp][1]);
                net[gsp][2] = fmaf(sg0, l0.z, net[gsp][2]);
                net[gsp][3] = fmaf(sg0, l0.w, net[gsp][3]);
                net[gsp][4] = fmaf(sg0, h0.x, net[gsp][4]);
                net[gsp][5] = fmaf(sg0, h0.y, net[gsp][5]);
                net[gsp][6] = fmaf(sg0, h0.z, net[gsp][6]);
                net[gsp][7] = fmaf(sg0, h0.w, net[gsp][7]);
                net[gsp][0] = fmaf(sg1, l1.x, net[gsp][0]);
                net[gsp][1] = fmaf(sg1, l1.y, net[gsp][1]);
                net[gsp][2] = fmaf(sg1, l1.z, net[gsp][2]);
                net[gsp][3] = fmaf(sg1, l1.w, net[gsp][3]);
                net[gsp][4] = fmaf(sg1, h1.x, net[gsp][4]);
                net[gsp][5] = fmaf(sg1, h1.y, net[gsp][5]);
                net[gsp][6] = fmaf(sg1, h1.z, net[gsp][6]);
                net[gsp][7] = fmaf(sg1, h1.w, net[gsp][7]);
                if (surf) {                       // warp-uniform
                    if (i >= m) {
                        ng[0] += l0.x; ng[1] += l0.y; ng[2] += l0.z; ng[3] += l0.w;
                        ng[4] += h0.x; ng[5] += h0.y; ng[6] += h0.z; ng[7] += h0.w;
                    }
                    if (i + 1 >= m) {
                        ng[0] += l1.x; ng[1] += l1.y; ng[2] += l1.z; ng[3] += l1.w;
                        ng[4] += h1.x; ng[5] += h1.y; ng[6] += h1.z; ng[7] += h1.w;
                    }
                }
            }
        }
        __syncthreads();
    }

    // ---- reductions: per row {gain, loss, ysurf, ymant} (red/tot alias lbuf) ----
    float vals[32];
    #pragma unroll
    for (int v = 0; v < 32; v++) vals[v] = 0.f;
    #pragma unroll
    for (int gsp = 0; gsp < SPT; gsp++) {
        int s = tid + gsp * NT;
        float4 ya = ylo[s], yb = yhi[s];
        float yr[ROWS] = { ya.x, ya.y, ya.z, ya.w, yb.x, yb.y, yb.z, yb.w };
        if (isSurf[gsp]) {
            #pragma unroll
            for (int r = 0; r < ROWS; r++) {
                vals[4 * r + 0] += net[gsp][r] + ng[r];
                vals[4 * r + 1] += ng[r];
                vals[4 * r + 2] += yr[r];
            }
        } else if (isMant[gsp]) {
            #pragma unroll
            for (int r = 0; r < ROWS; r++) vals[4 * r + 3] += yr[r];
        }
    }
    {
        int lane = tid & 31, w = tid >> 5;
        #pragma unroll
        for (int v = 0; v < 32; v++) {
            float x = warp_red(vals[v]);
            if (lane == 0) red[v][w] = x;
        }
        __syncthreads();
        if (tid < 32) {
            float s = 0.f;
            #pragma unroll
            for (int i = 0; i < NT / 32; i++) s += red[tid][i];
            tot[tid] = s;
        }
        __syncthreads();
    }

    float ks2m[ROWS], km2s[ROWS];
    #pragma unroll
    for (int r = 0; r < ROWS; r++) {
        ks2m[r] = tot[4 * r + 0] / (tot[4 * r + 2] + 1e-10f);
        km2s[r] = tot[4 * r + 1] / (tot[4 * r + 3] + 1e-10f);
    }

    // ---- epilogue: surface<->mantle transfer + write out ----
    #pragma unroll
    for (int gsp = 0; gsp < SPT; gsp++) {
        int s = tid + gsp * NT;
        float dy[ROWS];
        #pragma unroll
        for (int r = 0; r < ROWS; r++) dy[r] = net[gsp][r];
        unsigned ds = (unsigned)(s - s0), dm = (unsigned)(s - m0);
        if (ds < NSS) {
            float4 ma = ylo[m0 + ds], mb = yhi[m0 + ds];
            float4 sa = ylo[s],       sb = yhi[s];
            float ymr[ROWS] = { ma.x, ma.y, ma.z, ma.w, mb.x, mb.y, mb.z, mb.w };
            float ysr[ROWS] = { sa.x, sa.y, sa.z, sa.w, sb.x, sb.y, sb.z, sb.w };
            #pragma unroll
            for (int r = 0; r < ROWS; r++) dy[r] += km2s[r] * ymr[r] - ks2m[r] * ysr[r];
        } else if (dm < NSS) {
            float4 sa = ylo[s0 + dm], sb = yhi[s0 + dm];
            float4 ma = ylo[s],       mb = yhi[s];
            float ysr[ROWS] = { sa.x, sa.y, sa.z, sa.w, sb.x, sb.y, sb.z, sb.w };
            float ymr[ROWS] = { ma.x, ma.y, ma.z, ma.w, mb.x, mb.y, mb.z, mb.w };
            #pragma unroll
            for (int r = 0; r < ROWS; r++) dy[r] += ks2m[r] * ysr[r] - km2s[r] * ymr[r];
        }
        #pragma unroll
        for (int r = 0; r < ROWS; r++)
            out[(size_t)(b0 + r) * SB + s] = dy[r];
    }
}

extern "C" void kernel_launch(void* const* d_in, const int* in_sizes, int n_in,
                              void* d_out, int out_size) {
    const float* t_in    = (const float*)d_in[0];
    const float* y_in    = (const float*)d_in[1];
    const float* den_gas = (const float*)d_in[2];
    const float* a1      = (const float*)d_in[3];
    const float* g1      = (const float*)d_in[4];
    const float* a2      = (const float*)d_in[5];
    const float* g2      = (const float*)d_in[6];
    const int*   r11     = (const int*)d_in[7];
    const int*   p1      = (const int*)d_in[8];
    const int*   r12     = (const int*)d_in[9];
    const int*   r22     = (const int*)d_in[10];
    const int*   p2      = (const int*)d_in[11];
    const int*   inds_s  = (const int*)d_in[12];
    const int*   inds_m  = (const int*)d_in[13];
    float*       out     = (float*)d_out;

    const int B = in_sizes[0];

    cudaFuncSetAttribute(three_phase_rhs,
                         cudaFuncAttributeMaxDynamicSharedMemorySize, SMEM_BYTES);

    k_count<<<(NROLES + 255) / 256, 256>>>(p1, r11, p2, r12, r22);
    k_scan <<<1, 1024>>>();
    k_fill <<<(NROLES + 255) / 256, 256>>>(p1, r11, p2, r12, r22);

    three_phase_rhs<<<B / ROWS, NT, SMEM_BYTES>>>(
        t_in, y_in, den_gas, a1, g1, a2, g2,
        r11, r12, r22, inds_s, inds_m, out);
}